// round 14
// baseline (speedup 1.0000x reference)
#include <cuda_runtime.h>
#include <cstdint>

// Problem shape: B=4, H=16, L=4096, D=64, S=128
#define B_ 4
#define H_ 16
#define L_ 4096
#define D_ 64
#define S_ 128

// Flag threshold: 2*(1.3e-3 * ||x||_max(=16) + 7e-4) with margin
#define FLAG_THR 0.0435f

// Precomputed fp16 codebook, SW128-swizzled, one 16KB tile per head.
__device__ uint4 g_cf16[H_][1024];

__device__ __forceinline__ uint32_t smem_to_u32(const void* p) {
    uint32_t a;
    asm("{ .reg .u64 t; cvta.to.shared.u64 t, %1; cvt.u32.u64 %0, t; }"
        : "=r"(a) : "l"(p));
    return a;
}
__device__ __forceinline__ uint32_t swz(uint32_t off) {   // SW128, 16B granules
    return off ^ ((off >> 3) & 0x70);
}
__device__ __forceinline__ uint32_t f16x2_pack(float lo, float hi) {
    uint32_t r;
    asm("cvt.rn.f16x2.f32 %0, %1, %2;" : "=r"(r) : "f"(hi), "f"(lo));
    return r;
}
__device__ __forceinline__ void cp_async16(uint32_t dst, const void* src) {
    asm volatile("cp.async.cg.shared.global [%0], [%1], 16;"
                 :: "r"(dst), "l"(src) : "memory");
}
__device__ __forceinline__ void ldsm_x4(uint32_t a, uint32_t r[4]) {
    asm volatile("ldmatrix.sync.aligned.m8n8.x4.shared.b16 {%0,%1,%2,%3}, [%4];"
                 : "=r"(r[0]), "=r"(r[1]), "=r"(r[2]), "=r"(r[3]) : "r"(a));
}
__device__ __forceinline__ void mma_f16(float d[4], const uint32_t a[4],
                                        uint32_t b0, uint32_t b1) {
    asm volatile(
        "mma.sync.aligned.m16n8k16.row.col.f32.f16.f16.f32 "
        "{%0,%1,%2,%3}, {%4,%5,%6,%7}, {%8,%9}, {%0,%1,%2,%3};"
        : "+f"(d[0]), "+f"(d[1]), "+f"(d[2]), "+f"(d[3])
        : "r"(a[0]), "r"(a[1]), "r"(a[2]), "r"(a[3]), "r"(b0), "r"(b1));
}
// Pack score+index into a max-reducible uint32 (bias, clamp>=0, clear low
// 7 mantissa bits, insert 127-idx for smallest-index tie-break).
__device__ __forceinline__ uint32_t packsc(float s, int key7) {
    return (__float_as_uint(fmaxf(s + 16.0f, 0.0f)) & 0xFFFFFF80u)
           | (uint32_t)key7;
}

// ---------- presplit: c -> fp16 swizzled global + out-tail copy of c ----------
__global__ void presplit_c_kernel(const float* __restrict__ c,
                                  float4* __restrict__ out_tail) {
    const int chunk = blockIdx.x * 256 + threadIdx.x;   // 16384 chunks of 8 floats
    const int h  = chunk >> 10;
    const int cr = (chunk >> 3) & 127;
    const int cc = chunk & 7;
    const float4* src = reinterpret_cast<const float4*>(
        c + (size_t)h * S_ * D_ + cr * 64 + cc * 8);
    const float4 v0 = src[0], v1 = src[1];
    uint4 w;
    w.x = f16x2_pack(v0.x, v0.y);
    w.y = f16x2_pack(v0.z, v0.w);
    w.z = f16x2_pack(v1.x, v1.y);
    w.w = f16x2_pack(v1.z, v1.w);
    g_cf16[h][swz((uint32_t)(cr * 128 + cc * 16)) >> 4] = w;
    out_tail[chunk * 2]     = v0;
    out_tail[chunk * 2 + 1] = v1;
}

// ---------------- smem layout (bytes) ----------------
#define SM_X1     0          // 16384  x fp16 (SW128)
#define SM_C1     16384      // 16384  c fp16 (SW128)
#define SM_CFP    32768      // 33280  c fp32, stride 65 floats/row (lazy-filled)
#define SM_U1     66048      // 2*128 u32 packed top1
#define SM_U2     67072      // 2*128 u32 packed top2
#define SM_FIDX   68096      // 128 i32
#define SM_FLAG   68608      // 128 i32 (flagged-token list)
#define SM_NF     69120      // counter
#define SM_TOTAL  69136

__global__ __launch_bounds__(256, 3)
void quant_hmma_kernel(const float* __restrict__ x,
                       const float* __restrict__ c,
                       float* __restrict__ out) {
    extern __shared__ char smem[];
    const uint32_t sb = smem_to_u32(smem);
    const int tid = threadIdx.x, wid = tid >> 5, lane = tid & 31;
    const int bh = blockIdx.y, h = bh & (H_ - 1);
    const size_t tok0 = (size_t)bh * L_ + (size_t)blockIdx.x * 128;

    float*    sm_cfp = reinterpret_cast<float*>(smem + SM_CFP);
    uint32_t* sm_u1  = reinterpret_cast<uint32_t*>(smem + SM_U1);
    uint32_t* sm_u2  = reinterpret_cast<uint32_t*>(smem + SM_U2);
    int*      sm_fi  = reinterpret_cast<int*>(smem + SM_FIDX);
    int*      sm_fl  = reinterpret_cast<int*>(smem + SM_FLAG);
    int*      sm_nf  = reinterpret_cast<int*>(smem + SM_NF);

    if (tid == 0) *sm_nf = 0;

    // --- async copy of precomputed fp16 codebook tile into smem (overlapped) ---
    {
        const uint4* gsrc = g_cf16[h];
        #pragma unroll
        for (int i = 0; i < 4; ++i) {
            const int j = tid + i * 256;
            cp_async16(sb + SM_C1 + j * 16, gsrc + j);
        }
        asm volatile("cp.async.commit_group;" ::: "memory");
    }

    // --- x tile [128 x 64] -> fp16 SW128 smem (no norm pass needed) ---
    {
        const float* xg = x + tok0 * D_;
        #pragma unroll
        for (int it = 0; it < 4; ++it) {
            const int j = tid + it * 256;
            const int row = j >> 3, cc = j & 7;
            const float4* src = reinterpret_cast<const float4*>(xg + row * 64 + cc * 8);
            const float4 v0 = src[0], v1 = src[1];
            uint4 w;
            w.x = f16x2_pack(v0.x, v0.y);
            w.y = f16x2_pack(v0.z, v0.w);
            w.z = f16x2_pack(v1.x, v1.y);
            w.w = f16x2_pack(v1.z, v1.w);
            *reinterpret_cast<uint4*>(smem + SM_X1 + swz((uint32_t)(row*128 + cc*16))) = w;
        }
    }

    // --- bulk-zero this CTA's one-hot output block (no predication) ---
    {
        float4* outv = reinterpret_cast<float4*>(out) + tok0 * (S_ / 4);
        const float4 z = make_float4(0.f, 0.f, 0.f, 0.f);
        #pragma unroll
        for (int i = tid; i < 128 * (S_ / 4); i += 256) outv[i] = z;
    }
    asm volatile("cp.async.wait_group 0;" ::: "memory");
    __syncthreads();

    // --- MMA: warp -> tokens [32*(wid>>1), +32), codes [64*(wid&1), +64),
    //     two sequential nb-half passes (halves live accumulators) ---
    const int tb = wid >> 1;
    const int ch = wid & 1;

    const int arow = lane & 15, acol = lane >> 4;
    const int brow_base = ch * 64 + ((lane >> 4) << 3) + (lane & 7);
    const int bcol = (lane >> 3) & 1;
    const int g = (lane >> 2) & 7, tig = lane & 3;

    uint32_t M1[4], M2[4];
    #pragma unroll
    for (int t = 0; t < 4; ++t) { M1[t] = 0u; M2[t] = 0u; }

    #pragma unroll 1
    for (int pass = 0; pass < 2; ++pass) {
        float d[2][4][4];
        #pragma unroll
        for (int m = 0; m < 2; ++m)
            #pragma unroll
            for (int nb = 0; nb < 4; ++nb)
                #pragma unroll
                for (int q = 0; q < 4; ++q) d[m][nb][q] = 0.f;

        #pragma unroll
        for (int k = 0; k < 4; ++k) {
            uint32_t af[2][4];
            #pragma unroll
            for (int m = 0; m < 2; ++m) {
                const uint32_t aoff =
                    swz((uint32_t)((tb*32 + m*16 + arow)*128 + (2*k + acol)*16));
                ldsm_x4(sb + SM_X1 + aoff, af[m]);
            }
            #pragma unroll
            for (int nbl = 0; nbl < 2; ++nbl) {
                const int nbp = pass * 2 + nbl;
                uint32_t bf[4];
                const uint32_t boff =
                    swz((uint32_t)((brow_base + nbp*16)*128 + (2*k + bcol)*16));
                ldsm_x4(sb + SM_C1 + boff, bf);
                #pragma unroll
                for (int m = 0; m < 2; ++m) {
                    mma_f16(d[m][2*nbl],   af[m], bf[0], bf[1]);
                    mma_f16(d[m][2*nbl+1], af[m], bf[2], bf[3]);
                }
            }
        }

        // fold 8 scores/token via packed umax trees (branch-free, log-depth)
        const int key_base = 127 - (ch * 64 + pass * 32 + 2 * tig);
        #pragma unroll
        for (int m = 0; m < 2; ++m) {
            #pragma unroll
            for (int r = 0; r < 2; ++r) {
                const int t = m * 2 + r;
                uint32_t u[8];
                #pragma unroll
                for (int nbl = 0; nbl < 4; ++nbl) {
                    u[2*nbl]   = packsc(d[m][nbl][2*r],   key_base - nbl*8);
                    u[2*nbl+1] = packsc(d[m][nbl][2*r+1], key_base - nbl*8 - 1);
                }
                const uint32_t h01 = max(u[0],u[1]), l01 = min(u[0],u[1]);
                const uint32_t h23 = max(u[2],u[3]), l23 = min(u[2],u[3]);
                const uint32_t h45 = max(u[4],u[5]), l45 = min(u[4],u[5]);
                const uint32_t h67 = max(u[6],u[7]), l67 = min(u[6],u[7]);
                const uint32_t hA = max(h01,h23);
                const uint32_t lA = max(min(h01,h23), max(l01,l23));
                const uint32_t hB = max(h45,h67);
                const uint32_t lB = max(min(h45,h67), max(l45,l67));
                const uint32_t m1 = max(hA,hB);
                const uint32_t m2 = max(min(hA,hB), max(lA,lB));
                M2[t] = max(max(M2[t], m2), min(M1[t], m1));
                M1[t] = max(M1[t], m1);
            }
        }
    }

    // --- quad merge (lanes sharing token rows), packed ---
    #pragma unroll
    for (int off = 1; off <= 2; off <<= 1) {
        #pragma unroll
        for (int t = 0; t < 4; ++t) {
            const uint32_t o1 = __shfl_xor_sync(0xffffffffu, M1[t], off);
            const uint32_t o2 = __shfl_xor_sync(0xffffffffu, M2[t], off);
            M2[t] = max(max(M2[t], o2), min(M1[t], o1));
            M1[t] = max(M1[t], o1);
        }
    }
    if (tig == 0) {
        #pragma unroll
        for (int m = 0; m < 2; ++m)
            #pragma unroll
            for (int r = 0; r < 2; ++r) {
                const int t = m * 2 + r;
                const int trow = tb * 32 + m * 16 + g + 8 * r;
                sm_u1[ch * 128 + trow] = M1[t];
                sm_u2[ch * 128 + trow] = M2[t];
            }
    }
    __syncthreads();

    // --- merge halves; build flagged-token LIST (gap < FLAG_THR, constant:
    //     ||x|| <= 16 holds with overwhelming certainty for N(0,1)^64) ---
    if (tid < 128) {
        const uint32_t a1 = sm_u1[tid], b1 = sm_u1[128 + tid];
        const uint32_t a2 = sm_u2[tid], b2 = sm_u2[128 + tid];
        const uint32_t U1 = max(a1, b1);
        const uint32_t U2 = max(min(a1, b1), max(a2, b2));
        sm_fi[tid] = 127 - (int)(U1 & 0x7Fu);
        const float f1 = __uint_as_float(U1 & 0xFFFFFF80u);
        const float f2 = __uint_as_float(U2 & 0xFFFFFF80u);
        if (f1 - f2 < FLAG_THR) {
            const int pos = atomicAdd(sm_nf, 1);
            sm_fl[pos] = tid;
        }
    }
    __syncthreads();

    const int nf = *sm_nf;
    if (nf) {
        // --- lazy CFP fill: c[h] fp32 -> smem stride 65 (conflict-free) ---
        {
            const float* cg = c + (size_t)h * S_ * D_;
            #pragma unroll
            for (int it = 0; it < 4; ++it) {
                const int j = tid + it * 256;      // 1024 chunks of 8 floats
                const int row = j >> 3, cc = j & 7;
                const float4* src =
                    reinterpret_cast<const float4*>(cg + row * 64 + cc * 8);
                const float4 v0 = src[0], v1 = src[1];
                float* dstf = sm_cfp + row * 65 + cc * 8;
                dstf[0] = v0.x; dstf[1] = v0.y; dstf[2] = v0.z; dstf[3] = v0.w;
                dstf[4] = v1.x; dstf[5] = v1.y; dstf[6] = v1.z; dstf[7] = v1.w;
            }
        }
        __syncthreads();

        // --- exact fp32 rescore: full 128 codes/token, CFP smem stride-65,
        //     sequential d-ascending fmaf chain (certified R10/R13) ---
        for (int f = wid; f < nf; f += 8) {
            const int t = sm_fl[f];
            const float4* xg4 =
                reinterpret_cast<const float4*>(x + (tok0 + t) * D_);
            float acc[4] = {0.f, 0.f, 0.f, 0.f};
            #pragma unroll
            for (int kk = 0; kk < 16; ++kk) {
                const float4 xv = xg4[kk];         // uniform -> broadcast
                #pragma unroll
                for (int q = 0; q < 4; ++q) {
                    const float* cv = sm_cfp + (lane + 32 * q) * 65 + 4 * kk;
                    acc[q] = fmaf(xv.x, cv[0], acc[q]);
                    acc[q] = fmaf(xv.y, cv[1], acc[q]);
                    acc[q] = fmaf(xv.z, cv[2], acc[q]);
                    acc[q] = fmaf(xv.w, cv[3], acc[q]);
                }
            }
            float best = acc[0];
            int   bi2  = lane;
            #pragma unroll
            for (int q = 1; q < 4; ++q) {
                const int code = lane + 32 * q;
                if (acc[q] > best) { best = acc[q]; bi2 = code; }
            }
            #pragma unroll
            for (int off = 16; off > 0; off >>= 1) {
                const float os = __shfl_xor_sync(0xffffffffu, best, off);
                const int   oi = __shfl_xor_sync(0xffffffffu, bi2, off);
                if (os > best || (os == best && oi < bi2)) { best = os; bi2 = oi; }
            }
            if (lane == 0) sm_fi[t] = bi2;
        }
        __syncthreads();
    }

    // --- scatter the ones (zeros already written before the mainloop) ---
    if (tid < 128)
        out[(tok0 + tid) * S_ + sm_fi[tid]] = 1.0f;
}

extern "C" void kernel_launch(void* const* d_in, const int* in_sizes, int n_in,
                              void* d_out, int out_size) {
    const float* x = (const float*)d_in[0];   // [B,H,L,D] fp32
    const float* c = (const float*)d_in[1];   // [H,S,D]  fp32
    float* out = (float*)d_out;

    // c -> fp16 swizzled global codebook + out-tail pass-through
    presplit_c_kernel<<<64, 256>>>(
        c, reinterpret_cast<float4*>(out + (size_t)B_ * H_ * L_ * S_));

    cudaFuncSetAttribute(quant_hmma_kernel,
                         cudaFuncAttributeMaxDynamicSharedMemorySize, SM_TOTAL);
    dim3 grid(L_ / 128, B_ * H_);             // (32, 64) = 2048 CTAs
    quant_hmma_kernel<<<grid, 256, SM_TOTAL>>>(x, c, out);
}

// round 15
// speedup vs baseline: 1.0041x; 1.0041x over previous
#include <cuda_runtime.h>
#include <cstdint>

// Problem shape: B=4, H=16, L=4096, D=64, S=128
#define B_ 4
#define H_ 16
#define L_ 4096
#define D_ 64
#define S_ 128

// Flag threshold: 2*(1.3e-3 * ||x||_max(=16) + 7e-4); ||x||<=16 holds with
// probability 1-1e-23 per token for N(0,1)^64 -> strict superset of the
// certified R13 per-token flags.
#define FLAG_THR 0.0435f

// Precomputed fp16 codebook, SW128-swizzled, one 16KB tile per head.
__device__ uint4 g_cf16[H_][1024];

__device__ __forceinline__ uint32_t smem_to_u32(const void* p) {
    uint32_t a;
    asm("{ .reg .u64 t; cvta.to.shared.u64 t, %1; cvt.u32.u64 %0, t; }"
        : "=r"(a) : "l"(p));
    return a;
}
__device__ __forceinline__ uint32_t swz(uint32_t off) {   // SW128, 16B granules
    return off ^ ((off >> 3) & 0x70);
}
__device__ __forceinline__ uint32_t f16x2_pack(float lo, float hi) {
    uint32_t r;
    asm("cvt.rn.f16x2.f32 %0, %1, %2;" : "=r"(r) : "f"(hi), "f"(lo));
    return r;
}
__device__ __forceinline__ void ldsm_x4(uint32_t a, uint32_t r[4]) {
    asm volatile("ldmatrix.sync.aligned.m8n8.x4.shared.b16 {%0,%1,%2,%3}, [%4];"
                 : "=r"(r[0]), "=r"(r[1]), "=r"(r[2]), "=r"(r[3]) : "r"(a));
}
__device__ __forceinline__ void mma_f16(float d[4], const uint32_t a[4],
                                        uint32_t b0, uint32_t b1) {
    asm volatile(
        "mma.sync.aligned.m16n8k16.row.col.f32.f16.f16.f32 "
        "{%0,%1,%2,%3}, {%4,%5,%6,%7}, {%8,%9}, {%0,%1,%2,%3};"
        : "+f"(d[0]), "+f"(d[1]), "+f"(d[2]), "+f"(d[3])
        : "r"(a[0]), "r"(a[1]), "r"(a[2]), "r"(a[3]), "r"(b0), "r"(b1));
}
// Pack score+index into a max-reducible uint32 (bias, clamp>=0, clear low
// 7 mantissa bits, insert 127-idx for smallest-index tie-break).
__device__ __forceinline__ uint32_t packsc(float s, int key7) {
    return (__float_as_uint(fmaxf(s + 16.0f, 0.0f)) & 0xFFFFFF80u)
           | (uint32_t)key7;
}

// ---------- presplit: c -> fp16 swizzled global + out-tail copy of c ----------
__global__ void presplit_c_kernel(const float* __restrict__ c,
                                  float4* __restrict__ out_tail) {
    const int chunk = blockIdx.x * 256 + threadIdx.x;   // 16384 chunks of 8 floats
    const int h  = chunk >> 10;
    const int cr = (chunk >> 3) & 127;
    const int cc = chunk & 7;
    const float4* src = reinterpret_cast<const float4*>(
        c + (size_t)h * S_ * D_ + cr * 64 + cc * 8);
    const float4 v0 = src[0], v1 = src[1];
    uint4 w;
    w.x = f16x2_pack(v0.x, v0.y);
    w.y = f16x2_pack(v0.z, v0.w);
    w.z = f16x2_pack(v1.x, v1.y);
    w.w = f16x2_pack(v1.z, v1.w);
    g_cf16[h][swz((uint32_t)(cr * 128 + cc * 16)) >> 4] = w;
    out_tail[chunk * 2]     = v0;
    out_tail[chunk * 2 + 1] = v1;
}

// ---------------- smem layout (bytes) ----------------
#define SM_X1     0          // 16384  x fp16 (SW128)
#define SM_C1     16384      // 16384  c fp16 (SW128)
#define SM_CFP    32768      // 33280  c fp32, stride 65 floats/row (conflict-free)
#define SM_U1     66048      // 2*128 u32 packed top1
#define SM_U2     67072      // 2*128 u32 packed top2
#define SM_FIDX   68096      // 128 i32
#define SM_FLAG   68608      // 128 i32 (flagged-token list)
#define SM_NF     69120      // counter
#define SM_TOTAL  69136

__global__ __launch_bounds__(256, 3)
void quant_hmma_kernel(const float* __restrict__ x,
                       const float* __restrict__ c,
                       float* __restrict__ out) {
    extern __shared__ char smem[];
    const uint32_t sb = smem_to_u32(smem);
    const int tid = threadIdx.x, wid = tid >> 5, lane = tid & 31;
    const int bh = blockIdx.y, h = bh & (H_ - 1);
    const size_t tok0 = (size_t)bh * L_ + (size_t)blockIdx.x * 128;

    float*    sm_cfp = reinterpret_cast<float*>(smem + SM_CFP);
    uint32_t* sm_u1  = reinterpret_cast<uint32_t*>(smem + SM_U1);
    uint32_t* sm_u2  = reinterpret_cast<uint32_t*>(smem + SM_U2);
    int*      sm_fi  = reinterpret_cast<int*>(smem + SM_FIDX);
    int*      sm_fl  = reinterpret_cast<int*>(smem + SM_FLAG);
    int*      sm_nf  = reinterpret_cast<int*>(smem + SM_NF);

    if (tid == 0) *sm_nf = 0;

    // --- copy precomputed fp16 codebook tile (already swizzled) into smem ---
    {
        const uint4* gsrc = g_cf16[h];
        uint4* dst = reinterpret_cast<uint4*>(smem + SM_C1);
        #pragma unroll
        for (int i = tid; i < 1024; i += 256) dst[i] = gsrc[i];
    }

    // --- c[h] fp32 -> CFP smem (stride 65, conflict-free for rescore) ---
    {
        const float* cg = c + (size_t)h * S_ * D_;
        #pragma unroll
        for (int it = 0; it < 4; ++it) {
            const int j = tid + it * 256;          // 1024 chunks of 8 floats
            const int row = j >> 3, cc = j & 7;
            const float4* src = reinterpret_cast<const float4*>(cg + row * 64 + cc * 8);
            const float4 v0 = src[0], v1 = src[1];
            float* dstf = sm_cfp + row * 65 + cc * 8;
            dstf[0] = v0.x; dstf[1] = v0.y; dstf[2] = v0.z; dstf[3] = v0.w;
            dstf[4] = v1.x; dstf[5] = v1.y; dstf[6] = v1.z; dstf[7] = v1.w;
        }
    }

    // --- x tile [128 x 64] -> fp16 SW128 smem (no norm pass) ---
    {
        const float* xg = x + tok0 * D_;
        #pragma unroll
        for (int it = 0; it < 4; ++it) {
            const int j = tid + it * 256;
            const int row = j >> 3, cc = j & 7;
            const float4* src = reinterpret_cast<const float4*>(xg + row * 64 + cc * 8);
            const float4 v0 = src[0], v1 = src[1];
            uint4 w;
            w.x = f16x2_pack(v0.x, v0.y);
            w.y = f16x2_pack(v0.z, v0.w);
            w.z = f16x2_pack(v1.x, v1.y);
            w.w = f16x2_pack(v1.z, v1.w);
            *reinterpret_cast<uint4*>(smem + SM_X1 + swz((uint32_t)(row*128 + cc*16))) = w;
        }
    }

    // --- bulk-zero this CTA's one-hot output block (no predication) ---
    {
        float4* outv = reinterpret_cast<float4*>(out) + tok0 * (S_ / 4);
        const float4 z = make_float4(0.f, 0.f, 0.f, 0.f);
        #pragma unroll
        for (int i = tid; i < 128 * (S_ / 4); i += 256) outv[i] = z;
    }
    __syncthreads();

    // --- MMA: warp -> tokens [32*(wid>>1), +32), codes [64*(wid&1), +64),
    //     two sequential nb-half passes (halves live accumulators) ---
    const int tb = wid >> 1;
    const int ch = wid & 1;

    const int arow = lane & 15, acol = lane >> 4;
    const int brow_base = ch * 64 + ((lane >> 4) << 3) + (lane & 7);
    const int bcol = (lane >> 3) & 1;
    const int g = (lane >> 2) & 7, tig = lane & 3;

    uint32_t M1[4], M2[4];
    #pragma unroll
    for (int t = 0; t < 4; ++t) { M1[t] = 0u; M2[t] = 0u; }

    #pragma unroll 1
    for (int pass = 0; pass < 2; ++pass) {
        float d[2][4][4];
        #pragma unroll
        for (int m = 0; m < 2; ++m)
            #pragma unroll
            for (int nb = 0; nb < 4; ++nb)
                #pragma unroll
                for (int q = 0; q < 4; ++q) d[m][nb][q] = 0.f;

        #pragma unroll
        for (int k = 0; k < 4; ++k) {
            uint32_t af[2][4];
            #pragma unroll
            for (int m = 0; m < 2; ++m) {
                const uint32_t aoff =
                    swz((uint32_t)((tb*32 + m*16 + arow)*128 + (2*k + acol)*16));
                ldsm_x4(sb + SM_X1 + aoff, af[m]);
            }
            #pragma unroll
            for (int nbl = 0; nbl < 2; ++nbl) {
                const int nbp = pass * 2 + nbl;
                uint32_t bf[4];
                const uint32_t boff =
                    swz((uint32_t)((brow_base + nbp*16)*128 + (2*k + bcol)*16));
                ldsm_x4(sb + SM_C1 + boff, bf);
                #pragma unroll
                for (int m = 0; m < 2; ++m) {
                    mma_f16(d[m][2*nbl],   af[m], bf[0], bf[1]);
                    mma_f16(d[m][2*nbl+1], af[m], bf[2], bf[3]);
                }
            }
        }

        // fold 8 scores/token via packed umax trees (branch-free, log-depth)
        const int key_base = 127 - (ch * 64 + pass * 32 + 2 * tig);
        #pragma unroll
        for (int m = 0; m < 2; ++m) {
            #pragma unroll
            for (int r = 0; r < 2; ++r) {
                const int t = m * 2 + r;
                uint32_t u[8];
                #pragma unroll
                for (int nbl = 0; nbl < 4; ++nbl) {
                    u[2*nbl]   = packsc(d[m][nbl][2*r],   key_base - nbl*8);
                    u[2*nbl+1] = packsc(d[m][nbl][2*r+1], key_base - nbl*8 - 1);
                }
                const uint32_t h01 = max(u[0],u[1]), l01 = min(u[0],u[1]);
                const uint32_t h23 = max(u[2],u[3]), l23 = min(u[2],u[3]);
                const uint32_t h45 = max(u[4],u[5]), l45 = min(u[4],u[5]);
                const uint32_t h67 = max(u[6],u[7]), l67 = min(u[6],u[7]);
                const uint32_t hA = max(h01,h23);
                const uint32_t lA = max(min(h01,h23), max(l01,l23));
                const uint32_t hB = max(h45,h67);
                const uint32_t lB = max(min(h45,h67), max(l45,l67));
                const uint32_t m1 = max(hA,hB);
                const uint32_t m2 = max(min(hA,hB), max(lA,lB));
                M2[t] = max(max(M2[t], m2), min(M1[t], m1));
                M1[t] = max(M1[t], m1);
            }
        }
    }

    // --- quad merge (lanes sharing token rows), packed ---
    #pragma unroll
    for (int off = 1; off <= 2; off <<= 1) {
        #pragma unroll
        for (int t = 0; t < 4; ++t) {
            const uint32_t o1 = __shfl_xor_sync(0xffffffffu, M1[t], off);
            const uint32_t o2 = __shfl_xor_sync(0xffffffffu, M2[t], off);
            M2[t] = max(max(M2[t], o2), min(M1[t], o1));
            M1[t] = max(M1[t], o1);
        }
    }
    if (tig == 0) {
        #pragma unroll
        for (int m = 0; m < 2; ++m)
            #pragma unroll
            for (int r = 0; r < 2; ++r) {
                const int t = m * 2 + r;
                const int trow = tb * 32 + m * 16 + g + 8 * r;
                sm_u1[ch * 128 + trow] = M1[t];
                sm_u2[ch * 128 + trow] = M2[t];
            }
    }
    __syncthreads();

    // --- merge halves; build flagged-token LIST (gap < FLAG_THR) ---
    if (tid < 128) {
        const uint32_t a1 = sm_u1[tid], b1 = sm_u1[128 + tid];
        const uint32_t a2 = sm_u2[tid], b2 = sm_u2[128 + tid];
        const uint32_t U1 = max(a1, b1);
        const uint32_t U2 = max(min(a1, b1), max(a2, b2));
        sm_fi[tid] = 127 - (int)(U1 & 0x7Fu);
        const float f1 = __uint_as_float(U1 & 0xFFFFFF80u);
        const float f2 = __uint_as_float(U2 & 0xFFFFFF80u);
        if (f1 - f2 < FLAG_THR) {
            const int pos = atomicAdd(sm_nf, 1);
            sm_fl[pos] = tid;
        }
    }
    __syncthreads();

    // --- exact fp32 rescore of flagged tokens (~1.7%), full 128 codes/token,
    //     CFP smem stride-65, sequential d-ascending fmaf (certified R10/R13) ---
    const int nf = *sm_nf;
    for (int f = wid; f < nf; f += 8) {
        const int t = sm_fl[f];
        const float4* xg4 = reinterpret_cast<const float4*>(x + (tok0 + t) * D_);
        float acc[4] = {0.f, 0.f, 0.f, 0.f};
        #pragma unroll
        for (int kk = 0; kk < 16; ++kk) {
            const float4 xv = xg4[kk];           // uniform -> broadcast
            #pragma unroll
            for (int q = 0; q < 4; ++q) {
                const float* cv = sm_cfp + (lane + 32 * q) * 65 + 4 * kk;
                acc[q] = fmaf(xv.x, cv[0], acc[q]);
                acc[q] = fmaf(xv.y, cv[1], acc[q]);
                acc[q] = fmaf(xv.z, cv[2], acc[q]);
                acc[q] = fmaf(xv.w, cv[3], acc[q]);
            }
        }
        float best = acc[0];
        int   bi2  = lane;
        #pragma unroll
        for (int q = 1; q < 4; ++q) {
            const int code = lane + 32 * q;
            if (acc[q] > best) { best = acc[q]; bi2 = code; }  // ascending idx
        }
        #pragma unroll
        for (int off = 16; off > 0; off >>= 1) {
            const float os = __shfl_xor_sync(0xffffffffu, best, off);
            const int   oi = __shfl_xor_sync(0xffffffffu, bi2, off);
            if (os > best || (os == best && oi < bi2)) { best = os; bi2 = oi; }
        }
        if (lane == 0) sm_fi[t] = bi2;
    }
    __syncthreads();

    // --- scatter the ones (zeros already written before the mainloop) ---
    if (tid < 128)
        out[(tok0 + tid) * S_ + sm_fi[tid]] = 1.0f;
}

extern "C" void kernel_launch(void* const* d_in, const int* in_sizes, int n_in,
                              void* d_out, int out_size) {
    const float* x = (const float*)d_in[0];   // [B,H,L,D] fp32
    const float* c = (const float*)d_in[1];   // [H,S,D]  fp32
    float* out = (float*)d_out;

    // c -> fp16 swizzled global codebook + out-tail pass-through
    presplit_c_kernel<<<64, 256>>>(
        c, reinterpret_cast<float4*>(out + (size_t)B_ * H_ * L_ * S_));

    cudaFuncSetAttribute(quant_hmma_kernel,
                         cudaFuncAttributeMaxDynamicSharedMemorySize, SM_TOTAL);
    dim3 grid(L_ / 128, B_ * H_);             // (32, 64) = 2048 CTAs
    quant_hmma_kernel<<<grid, 256, SM_TOTAL>>>(x, c, out);
}

// round 16
// speedup vs baseline: 1.2021x; 1.1973x over previous
#include <cuda_runtime.h>
#include <cstdint>

// Problem shape: B=4, H=16, L=4096, D=64, S=128
#define B_ 4
#define H_ 16
#define L_ 4096
#define D_ 64
#define S_ 128

// Precomputed fp16 codebook, SW128-swizzled, one 16KB tile per head.
__device__ uint4 g_cf16[H_][1024];

__device__ __forceinline__ uint32_t smem_to_u32(const void* p) {
    uint32_t a;
    asm("{ .reg .u64 t; cvta.to.shared.u64 t, %1; cvt.u32.u64 %0, t; }"
        : "=r"(a) : "l"(p));
    return a;
}
__device__ __forceinline__ uint32_t swz(uint32_t off) {   // SW128, 16B granules
    return off ^ ((off >> 3) & 0x70);
}
__device__ __forceinline__ uint32_t f16x2_pack(float lo, float hi) {
    uint32_t r;
    asm("cvt.rn.f16x2.f32 %0, %1, %2;" : "=r"(r) : "f"(hi), "f"(lo));
    return r;
}
__device__ __forceinline__ void ldsm_x4(uint32_t a, uint32_t r[4]) {
    asm volatile("ldmatrix.sync.aligned.m8n8.x4.shared.b16 {%0,%1,%2,%3}, [%4];"
                 : "=r"(r[0]), "=r"(r[1]), "=r"(r[2]), "=r"(r[3]) : "r"(a));
}
__device__ __forceinline__ void mma_f16(float d[4], const uint32_t a[4],
                                        uint32_t b0, uint32_t b1) {
    asm volatile(
        "mma.sync.aligned.m16n8k16.row.col.f32.f16.f16.f32 "
        "{%0,%1,%2,%3}, {%4,%5,%6,%7}, {%8,%9}, {%0,%1,%2,%3};"
        : "+f"(d[0]), "+f"(d[1]), "+f"(d[2]), "+f"(d[3])
        : "r"(a[0]), "r"(a[1]), "r"(a[2]), "r"(a[3]), "r"(b0), "r"(b1));
}
// Pack score+index into a max-reducible uint32 (bias, clamp>=0, clear low
// 7 mantissa bits, insert 127-idx for smallest-index tie-break).
__device__ __forceinline__ uint32_t packsc(float s, int key7) {
    return (__float_as_uint(fmaxf(s + 16.0f, 0.0f)) & 0xFFFFFF80u)
           | (uint32_t)key7;
}

// ---------- presplit: c -> fp16 swizzled global + out-tail copy of c ----------
__global__ void presplit_c_kernel(const float* __restrict__ c,
                                  float4* __restrict__ out_tail) {
    const int chunk = blockIdx.x * 256 + threadIdx.x;   // 16384 chunks of 8 floats
    const int h  = chunk >> 10;
    const int cr = (chunk >> 3) & 127;
    const int cc = chunk & 7;
    const float4* src = reinterpret_cast<const float4*>(
        c + (size_t)h * S_ * D_ + cr * 64 + cc * 8);
    const float4 v0 = src[0], v1 = src[1];
    uint4 w;
    w.x = f16x2_pack(v0.x, v0.y);
    w.y = f16x2_pack(v0.z, v0.w);
    w.z = f16x2_pack(v1.x, v1.y);
    w.w = f16x2_pack(v1.z, v1.w);
    g_cf16[h][swz((uint32_t)(cr * 128 + cc * 16)) >> 4] = w;
    out_tail[chunk * 2]     = v0;
    out_tail[chunk * 2 + 1] = v1;
}

// ---------------- smem layout (bytes) ----------------
#define SM_X1     0          // 16384  x fp16 (SW128), reused per batch
#define SM_C1     16384      // 16384  c fp16 (SW128), shared by both batches
#define SM_CFP    32768      // 33280  c fp32, stride 65 (shared by both batches)
#define SM_XN2    66048      // 128 f32
#define SM_U1     66560      // 2*128 u32 packed top1
#define SM_U2     67584      // 2*128 u32 packed top2
#define SM_FIDX   68608      // 128 i32
#define SM_FLAG   69120      // 128 i32 (flagged-token list)
#define SM_NF     69632      // counter
#define SM_TOTAL  69648

__global__ __launch_bounds__(256, 3)
void quant_hmma_kernel(const float* __restrict__ x,
                       const float* __restrict__ c,
                       float* __restrict__ out) {
    extern __shared__ char smem[];
    const uint32_t sb = smem_to_u32(smem);
    const int tid = threadIdx.x, wid = tid >> 5, lane = tid & 31;
    const int bh = blockIdx.y, h = bh & (H_ - 1);

    float*    sm_cfp = reinterpret_cast<float*>(smem + SM_CFP);
    float*    sm_xn2 = reinterpret_cast<float*>(smem + SM_XN2);
    uint32_t* sm_u1  = reinterpret_cast<uint32_t*>(smem + SM_U1);
    uint32_t* sm_u2  = reinterpret_cast<uint32_t*>(smem + SM_U2);
    int*      sm_fi  = reinterpret_cast<int*>(smem + SM_FIDX);
    int*      sm_fl  = reinterpret_cast<int*>(smem + SM_FLAG);
    int*      sm_nf  = reinterpret_cast<int*>(smem + SM_NF);

    // --- fixed per-CTA fills (amortized over BOTH token batches) ---
    {
        const uint4* gsrc = g_cf16[h];
        uint4* dst = reinterpret_cast<uint4*>(smem + SM_C1);
        #pragma unroll
        for (int i = tid; i < 1024; i += 256) dst[i] = gsrc[i];
    }
    {
        const float* cg = c + (size_t)h * S_ * D_;
        #pragma unroll
        for (int it = 0; it < 4; ++it) {
            const int j = tid + it * 256;          // 1024 chunks of 8 floats
            const int row = j >> 3, cc = j & 7;
            const float4* src = reinterpret_cast<const float4*>(cg + row * 64 + cc * 8);
            const float4 v0 = src[0], v1 = src[1];
            float* dstf = sm_cfp + row * 65 + cc * 8;
            dstf[0] = v0.x; dstf[1] = v0.y; dstf[2] = v0.z; dstf[3] = v0.w;
            dstf[4] = v1.x; dstf[5] = v1.y; dstf[6] = v1.z; dstf[7] = v1.w;
        }
    }

    // lane-constant address components
    const int tb = wid >> 1;
    const int ch = wid & 1;
    const int arow = lane & 15, acol = lane >> 4;
    const int brow_base = ch * 64 + ((lane >> 4) << 3) + (lane & 7);
    const int bcol = (lane >> 3) & 1;
    const int g = (lane >> 2) & 7, tig = lane & 3;

    #pragma unroll 1
    for (int batch = 0; batch < 2; ++batch) {
        const size_t tok0 =
            (size_t)bh * L_ + (size_t)blockIdx.x * 256 + (size_t)batch * 128;

        if (tid == 0) *sm_nf = 0;

        // --- x tile [128 x 64] -> fp16 SW128 smem + per-token ||x||^2 ---
        {
            const float* xg = x + tok0 * D_;
            #pragma unroll
            for (int it = 0; it < 4; ++it) {
                const int j = tid + it * 256;
                const int row = j >> 3, cc = j & 7;
                const float4* src =
                    reinterpret_cast<const float4*>(xg + row * 64 + cc * 8);
                const float4 v0 = src[0], v1 = src[1];
                float nrm = v0.x*v0.x + v0.y*v0.y;
                nrm = fmaf(v0.z, v0.z, nrm); nrm = fmaf(v0.w, v0.w, nrm);
                nrm = fmaf(v1.x, v1.x, nrm); nrm = fmaf(v1.y, v1.y, nrm);
                nrm = fmaf(v1.z, v1.z, nrm); nrm = fmaf(v1.w, v1.w, nrm);
                nrm += __shfl_xor_sync(0xffffffffu, nrm, 1);
                nrm += __shfl_xor_sync(0xffffffffu, nrm, 2);
                nrm += __shfl_xor_sync(0xffffffffu, nrm, 4);
                if ((lane & 7) == 0) sm_xn2[row] = nrm;
                uint4 w;
                w.x = f16x2_pack(v0.x, v0.y);
                w.y = f16x2_pack(v0.z, v0.w);
                w.z = f16x2_pack(v1.x, v1.y);
                w.w = f16x2_pack(v1.z, v1.w);
                *reinterpret_cast<uint4*>(
                    smem + SM_X1 + swz((uint32_t)(row*128 + cc*16))) = w;
            }
        }

        // --- bulk-zero this batch's one-hot output block ---
        {
            float4* outv = reinterpret_cast<float4*>(out) + tok0 * (S_ / 4);
            const float4 z = make_float4(0.f, 0.f, 0.f, 0.f);
            #pragma unroll
            for (int i = tid; i < 128 * (S_ / 4); i += 256) outv[i] = z;
        }
        __syncthreads();

        // --- MMA mainloop: two nb-half passes, packed top-2 fold ---
        uint32_t M1[4], M2[4];
        #pragma unroll
        for (int t = 0; t < 4; ++t) { M1[t] = 0u; M2[t] = 0u; }

        #pragma unroll 1
        for (int pass = 0; pass < 2; ++pass) {
            float d[2][4][4];
            #pragma unroll
            for (int m = 0; m < 2; ++m)
                #pragma unroll
                for (int nb = 0; nb < 4; ++nb)
                    #pragma unroll
                    for (int q = 0; q < 4; ++q) d[m][nb][q] = 0.f;

            #pragma unroll
            for (int k = 0; k < 4; ++k) {
                uint32_t af[2][4];
                #pragma unroll
                for (int m = 0; m < 2; ++m) {
                    const uint32_t aoff =
                        swz((uint32_t)((tb*32 + m*16 + arow)*128 + (2*k + acol)*16));
                    ldsm_x4(sb + SM_X1 + aoff, af[m]);
                }
                #pragma unroll
                for (int nbl = 0; nbl < 2; ++nbl) {
                    const int nbp = pass * 2 + nbl;
                    uint32_t bf[4];
                    const uint32_t boff =
                        swz((uint32_t)((brow_base + nbp*16)*128 + (2*k + bcol)*16));
                    ldsm_x4(sb + SM_C1 + boff, bf);
                    #pragma unroll
                    for (int m = 0; m < 2; ++m) {
                        mma_f16(d[m][2*nbl],   af[m], bf[0], bf[1]);
                        mma_f16(d[m][2*nbl+1], af[m], bf[2], bf[3]);
                    }
                }
            }

            const int key_base = 127 - (ch * 64 + pass * 32 + 2 * tig);
            #pragma unroll
            for (int m = 0; m < 2; ++m) {
                #pragma unroll
                for (int r = 0; r < 2; ++r) {
                    const int t = m * 2 + r;
                    uint32_t u[8];
                    #pragma unroll
                    for (int nbl = 0; nbl < 4; ++nbl) {
                        u[2*nbl]   = packsc(d[m][nbl][2*r],   key_base - nbl*8);
                        u[2*nbl+1] = packsc(d[m][nbl][2*r+1], key_base - nbl*8 - 1);
                    }
                    const uint32_t h01 = max(u[0],u[1]), l01 = min(u[0],u[1]);
                    const uint32_t h23 = max(u[2],u[3]), l23 = min(u[2],u[3]);
                    const uint32_t h45 = max(u[4],u[5]), l45 = min(u[4],u[5]);
                    const uint32_t h67 = max(u[6],u[7]), l67 = min(u[6],u[7]);
                    const uint32_t hA = max(h01,h23);
                    const uint32_t lA = max(min(h01,h23), max(l01,l23));
                    const uint32_t hB = max(h45,h67);
                    const uint32_t lB = max(min(h45,h67), max(l45,l67));
                    const uint32_t m1 = max(hA,hB);
                    const uint32_t m2 = max(min(hA,hB), max(lA,lB));
                    M2[t] = max(max(M2[t], m2), min(M1[t], m1));
                    M1[t] = max(M1[t], m1);
                }
            }
        }

        // --- quad merge (lanes sharing token rows), packed ---
        #pragma unroll
        for (int off = 1; off <= 2; off <<= 1) {
            #pragma unroll
            for (int t = 0; t < 4; ++t) {
                const uint32_t o1 = __shfl_xor_sync(0xffffffffu, M1[t], off);
                const uint32_t o2 = __shfl_xor_sync(0xffffffffu, M2[t], off);
                M2[t] = max(max(M2[t], o2), min(M1[t], o1));
                M1[t] = max(M1[t], o1);
            }
        }
        if (tig == 0) {
            #pragma unroll
            for (int m = 0; m < 2; ++m)
                #pragma unroll
                for (int r = 0; r < 2; ++r) {
                    const int t = m * 2 + r;
                    const int trow = tb * 32 + m * 16 + g + 8 * r;
                    sm_u1[ch * 128 + trow] = M1[t];
                    sm_u2[ch * 128 + trow] = M2[t];
                }
        }
        __syncthreads();

        // --- merge halves; flag tokens (gap < 2*eps, per-token ||x||) ---
        if (tid < 128) {
            const uint32_t a1 = sm_u1[tid], b1 = sm_u1[128 + tid];
            const uint32_t a2 = sm_u2[tid], b2 = sm_u2[128 + tid];
            const uint32_t U1 = max(a1, b1);
            const uint32_t U2 = max(min(a1, b1), max(a2, b2));
            sm_fi[tid] = 127 - (int)(U1 & 0x7Fu);
            const float f1 = __uint_as_float(U1 & 0xFFFFFF80u);
            const float f2 = __uint_as_float(U2 & 0xFFFFFF80u);
            const float eps = 1.3e-3f * sqrtf(sm_xn2[tid]) + 7.0e-4f;
            if (f1 - f2 < 2.f * eps) {
                const int pos = atomicAdd(sm_nf, 1);
                sm_fl[pos] = tid;
            }
        }
        __syncthreads();

        // --- exact fp32 rescore of flagged tokens (certified R10/R13 path) ---
        const int nf = *sm_nf;
        for (int f = wid; f < nf; f += 8) {
            const int t = sm_fl[f];
            const float4* xg4 =
                reinterpret_cast<const float4*>(x + (tok0 + t) * D_);
            float acc[4] = {0.f, 0.f, 0.f, 0.f};
            #pragma unroll
            for (int kk = 0; kk < 16; ++kk) {
                const float4 xv = xg4[kk];           // uniform -> broadcast
                #pragma unroll
                for (int q = 0; q < 4; ++q) {
                    const float* cv = sm_cfp + (lane + 32 * q) * 65 + 4 * kk;
                    acc[q] = fmaf(xv.x, cv[0], acc[q]);
                    acc[q] = fmaf(xv.y, cv[1], acc[q]);
                    acc[q] = fmaf(xv.z, cv[2], acc[q]);
                    acc[q] = fmaf(xv.w, cv[3], acc[q]);
                }
            }
            float best = acc[0];
            int   bi2  = lane;
            #pragma unroll
            for (int q = 1; q < 4; ++q) {
                const int code = lane + 32 * q;
                if (acc[q] > best) { best = acc[q]; bi2 = code; }
            }
            #pragma unroll
            for (int off = 16; off > 0; off >>= 1) {
                const float os = __shfl_xor_sync(0xffffffffu, best, off);
                const int   oi = __shfl_xor_sync(0xffffffffu, bi2, off);
                if (os > best || (os == best && oi < bi2)) { best = os; bi2 = oi; }
            }
            if (lane == 0) sm_fi[t] = bi2;
        }
        __syncthreads();

        // --- scatter the ones (zeros already written) ---
        if (tid < 128)
            out[(tok0 + tid) * S_ + sm_fi[tid]] = 1.0f;
        __syncthreads();
    }
}

extern "C" void kernel_launch(void* const* d_in, const int* in_sizes, int n_in,
                              void* d_out, int out_size) {
    const float* x = (const float*)d_in[0];   // [B,H,L,D] fp32
    const float* c = (const float*)d_in[1];   // [H,S,D]  fp32
    float* out = (float*)d_out;

    // c -> fp16 swizzled global codebook + out-tail pass-through
    presplit_c_kernel<<<64, 256>>>(
        c, reinterpret_cast<float4*>(out + (size_t)B_ * H_ * L_ * S_));

    cudaFuncSetAttribute(quant_hmma_kernel,
                         cudaFuncAttributeMaxDynamicSharedMemorySize, SM_TOTAL);
    dim3 grid(L_ / 256, B_ * H_);             // (16, 64) = 1024 CTAs, 2 batches
    quant_hmma_kernel<<<grid, 256, SM_TOTAL>>>(x, c, out);
}